// round 11
// baseline (speedup 1.0000x reference)
#include <cuda_runtime.h>
#include <cstdint>

#define BATCH 32
#define SEQ   512
#define DIMK  64
#define DPITCH 1024
#define BIGF  1e30f
#define L2E   1.4426950408889634f
#define LN2   0.6931471805599453f

// Diagonal-major distance scratch: Ddiag[b][p][i] = D[b, i, p-i]  (64 MB)
__device__ float g_Ddiag[BATCH * DPITCH * SEQ];

__device__ __forceinline__ float ex2f(float x) {
  float r; asm("ex2.approx.f32 %0, %1;" : "=f"(r) : "f"(x)); return r;
}
__device__ __forceinline__ float lg2f(float x) {
  float r; asm("lg2.approx.f32 %0, %1;" : "=f"(r) : "f"(x)); return r;
}
// softmin (base-2 domain): exact min/median/max; 2 EX2 + 1 LG2.
__device__ __forceinline__ float softmin3s(float a, float b, float c) {
  float u = fminf(a, b), v = fmaxf(a, b);
  float mn = fminf(u, c);
  float mx = fmaxf(v, c);
  float md = fmaxf(u, fminf(v, c));
  float s = 1.0f + ex2f(mn - md) + ex2f(mn - mx);
  return mn - lg2f(s);
}

// ---------------------------------------------------------------------------
// Phase 1: D = x2 + y2 - 2 x.y, diagonal-major output.
// 128x128 tile per CTA (R2's reuse: X read 4x, Y 4x), j processed in four
// 32-wide chunks staged via Dst[128][33] so diag-major stores are <=32-float
// (128B) coalesced runs (R10's store path). Grid (4, 4, 32) = 512 CTAs.
// ---------------------------------------------------------------------------
#define TI 128
#define TJ 128
#define YS_STRIDE 132
#define DST_STRIDE 33

__global__ __launch_bounds__(128) void gemm_diag_kernel(
    const float* __restrict__ X, const float* __restrict__ Y) {
  __shared__ float Ys[DIMK * YS_STRIDE];   // [k][j], 128 wide
  __shared__ float y2s[TJ];
  __shared__ float Dst[TI * DST_STRIDE];   // staging for one 128x32 chunk

  const int t = threadIdx.x;
  const int w = t >> 5, lane = t & 31;
  const int i0 = blockIdx.x << 7;   // 0,128,256,384
  const int j0 = blockIdx.y << 7;   // 0,128,256,384
  const int b  = blockIdx.z;

  const float* Xb = X + ((size_t)b * SEQ + i0) * DIMK;
  const float* Yb = Y + ((size_t)b * SEQ + j0) * DIMK;

  // Y tile transposed into smem (coalesced global reads).
  for (int e = t; e < TJ * DIMK; e += 128) {
    int j = e >> 6;
    int kk = e & 63;
    Ys[kk * YS_STRIDE + j] = Yb[e];
  }

  // X row -> registers, plus x2.
  float xr[DIMK];
  float x2 = 0.f;
#pragma unroll
  for (int k4 = 0; k4 < DIMK; k4 += 4) {
    float4 v = *reinterpret_cast<const float4*>(Xb + (size_t)t * DIMK + k4);
    xr[k4] = v.x; xr[k4 + 1] = v.y; xr[k4 + 2] = v.z; xr[k4 + 3] = v.w;
  }
#pragma unroll
  for (int kk = 0; kk < DIMK; kk++) x2 += xr[kk] * xr[kk];

  __syncthreads();

  // y2 per column (thread t handles column t).
  {
    float a = 0.f;
#pragma unroll
    for (int kk = 0; kk < DIMK; kk++) {
      float yv = Ys[kk * YS_STRIDE + t];
      a += yv * yv;
    }
    y2s[t] = a;
  }
  __syncthreads();

  float* gout = g_Ddiag + (size_t)b * (DPITCH * SEQ);

  for (int jc = 0; jc < 4; jc++) {
    // compute this 128x32 chunk in four 8-col sub-blocks (acc[8] -> no spill)
    for (int jb = 0; jb < 4; jb++) {
      const int jcol = jc * 32 + jb * 8;
      float acc[8];
#pragma unroll
      for (int m = 0; m < 8; m++) acc[m] = 0.f;
#pragma unroll
      for (int kk = 0; kk < DIMK; kk++) {
        const float4 ya = *reinterpret_cast<const float4*>(&Ys[kk * YS_STRIDE + jcol]);
        const float4 yb = *reinterpret_cast<const float4*>(&Ys[kk * YS_STRIDE + jcol + 4]);
        const float xv = xr[kk];
        acc[0] += xv * ya.x; acc[1] += xv * ya.y;
        acc[2] += xv * ya.z; acc[3] += xv * ya.w;
        acc[4] += xv * yb.x; acc[5] += xv * yb.y;
        acc[6] += xv * yb.z; acc[7] += xv * yb.w;
      }
#pragma unroll
      for (int m = 0; m < 8; m++) {
        Dst[t * DST_STRIDE + jb * 8 + m] = x2 + y2s[jcol + m] - 2.f * acc[m];
      }
    }
    __syncthreads();

    // diag-major store: chunk diag d = i + jloc in [0, 158], runs up to 32
    const int p0 = i0 + j0 + jc * 32;
    for (int d = w; d < TI + 32 - 1; d += 4) {
      int lo = d - 31 > 0 ? d - 31 : 0;
      int hi = d < TI - 1 ? d : TI - 1;
      int i = lo + lane;
      if (i <= hi) {
        gout[(size_t)(p0 + d) * SEQ + (i0 + i)] =
            Dst[i * DST_STRIDE + (d - i)];
      }
    }
    __syncthreads();
  }
}

// ---------------------------------------------------------------------------
// Phase 2: wavefront DP — R2 verbatim (reproduced at 135.1us, regs=93).
// 4 warps, 4 consecutive rows per thread; parity-double-buffered smem
// mailboxes; one barrier per step; 8-deep float4 register prefetch.
// Base-2 scaled domain (R' = R * log2e).
// ---------------------------------------------------------------------------
__global__ __launch_bounds__(128) void softdtw_dp_kernel(float* __restrict__ out) {
  const int b = blockIdx.x;
  const int t = threadIdx.x;
  const int lane = t & 31, w = t >> 5;

  __shared__ float sb1[2][4];
  __shared__ float sb2[2][4];
  if (t < 8) {
    (&sb1[0][0])[t] = BIGF;
    (&sb2[0][0])[t] = BIGF;
  }

  float v1[4], v2[4];
#pragma unroll
  for (int k = 0; k < 4; k++) { v1[k] = BIGF; v2[k] = BIGF; }

  const float* base = g_Ddiag + (size_t)b * (DPITCH * SEQ) + 4 * t;
  __syncthreads();

#define DP_STEP(P, G4)                                                        \
  {                                                                           \
    const int rs = (P) & 1;                                                   \
    float nb1 = __shfl_up_sync(0xffffffffu, v1[3], 1);                        \
    float nb2 = __shfl_up_sync(0xffffffffu, v2[3], 1);                        \
    if (lane == 0) {                                                          \
      nb1 = (w == 0) ? BIGF : sb1[rs][w - 1];                                 \
      nb2 = (w == 0) ? (((P) == 0) ? 0.0f : BIGF) : sb2[rs][w - 1];           \
    }                                                                         \
    float sm0 = softmin3s(nb2,   nb1,   v1[0]);                               \
    float sm1 = softmin3s(v2[0], v1[0], v1[1]);                               \
    float sm2 = softmin3s(v2[1], v1[1], v1[2]);                               \
    float sm3 = softmin3s(v2[2], v1[2], v1[3]);                               \
    unsigned pr = (unsigned)((P) - 4 * t);                                    \
    float n0 = (pr      < (unsigned)SEQ) ? fmaf((G4).x, L2E, sm0) : BIGF;     \
    float n1 = (pr - 1u < (unsigned)SEQ) ? fmaf((G4).y, L2E, sm1) : BIGF;     \
    float n2 = (pr - 2u < (unsigned)SEQ) ? fmaf((G4).z, L2E, sm2) : BIGF;     \
    float n3 = (pr - 3u < (unsigned)SEQ) ? fmaf((G4).w, L2E, sm3) : BIGF;     \
    v2[0] = v1[0]; v2[1] = v1[1]; v2[2] = v1[2]; v2[3] = v1[3];               \
    v1[0] = n0;    v1[1] = n1;    v1[2] = n2;    v1[3] = n3;                  \
    if (lane == 31) { sb1[rs ^ 1][w] = v1[3]; sb2[rs ^ 1][w] = v2[3]; }       \
    __syncthreads();                                                          \
  }

  // prefetch pipeline: groups of 8 diagonals
  float4 cur[8];
#pragma unroll
  for (int j = 0; j < 8; j++)
    cur[j] = *reinterpret_cast<const float4*>(base + (size_t)j * SEQ);

  for (int g = 0; g < 127; ++g) {
    float4 nxt[8];
#pragma unroll
    for (int j = 0; j < 8; j++)
      nxt[j] = *reinterpret_cast<const float4*>(base + (size_t)(8 * (g + 1) + j) * SEQ);
#pragma unroll
    for (int j = 0; j < 8; j++) {
      const int p = 8 * g + j;
      DP_STEP(p, cur[j]);
    }
#pragma unroll
    for (int j = 0; j < 8; j++) cur[j] = nxt[j];
  }
  // epilogue: p = 1016 .. 1022
#pragma unroll
  for (int j = 0; j < 7; j++) {
    const int p = 1016 + j;
    DP_STEP(p, cur[j]);
  }

  if (t == 127) out[b] = v1[3] * LN2;  // R(511,511), back to nat domain
#undef DP_STEP
}

// ---------------------------------------------------------------------------
extern "C" void kernel_launch(void* const* d_in, const int* in_sizes, int n_in,
                              void* d_out, int out_size) {
  const float* X = (const float*)d_in[0];
  const float* Y = (const float*)d_in[1];
  float* out = (float*)d_out;

  dim3 grid_g(4, 4, BATCH);     // 512 tiles of 128 x 128
  gemm_diag_kernel<<<grid_g, 128>>>(X, Y);
  softdtw_dp_kernel<<<BATCH, 128>>>(out);
}

// round 12
// speedup vs baseline: 1.1819x; 1.1819x over previous
#include <cuda_runtime.h>
#include <cstdint>

#define BATCH 32
#define SEQ   512
#define DIMK  64
#define DPITCH 1024
#define BIGF  1e30f
#define L2E   1.4426950408889634f
#define LN2   0.6931471805599453f

// Diagonal-major distance scratch: Ddiag[b][p][i] = D[b, i, p-i]  (64 MB)
__device__ float g_Ddiag[BATCH * DPITCH * SEQ];

__device__ __forceinline__ float ex2f(float x) {
  float r; asm("ex2.approx.f32 %0, %1;" : "=f"(r) : "f"(x)); return r;
}
__device__ __forceinline__ float lg2f(float x) {
  float r; asm("lg2.approx.f32 %0, %1;" : "=f"(r) : "f"(x)); return r;
}
// softmin (base-2 domain): exact min/median/max; 2 EX2 + 1 LG2.
__device__ __forceinline__ float softmin3s(float a, float b, float c) {
  float u = fminf(a, b), v = fmaxf(a, b);
  float mn = fminf(u, c);
  float mx = fmaxf(v, c);
  float md = fmaxf(u, fminf(v, c));
  float s = 1.0f + ex2f(mn - md) + ex2f(mn - mx);
  return mn - lg2f(s);
}

// ---------------------------------------------------------------------------
// Phase 1: D = x2 + y2 - 2 x.y, diagonal-major output.
// R7/R4 GEMM verbatim (best measured, ~51us): 256 threads, 128x128 tile,
// halves split the 16 j-blocks (8 each), per-half 128x8 staging.
// ---------------------------------------------------------------------------
#define TI 128
#define TJ 128
#define YS_STRIDE 132
#define DST_STRIDE 9

__global__ __launch_bounds__(256) void gemm_diag_kernel(
    const float* __restrict__ X, const float* __restrict__ Y) {
  const int t    = threadIdx.x;
  const int half = t >> 7;
  const int tt   = t & 127;
  const int i0 = blockIdx.x * TI;
  const int j0 = blockIdx.y * TJ;
  const int b  = blockIdx.z;

  __shared__ float Ys[DIMK * YS_STRIDE];     // [k][j]
  __shared__ float y2s[TJ];
  __shared__ float Dst[2][TI * DST_STRIDE];  // per-half staging

  const float* Xb = X + ((size_t)b * SEQ + i0) * DIMK;
  const float* Yb = Y + ((size_t)b * SEQ + j0) * DIMK;

  for (int e = t; e < TJ * DIMK; e += 256) {
    int j = e >> 6;
    int k = e & 63;
    Ys[k * YS_STRIDE + j] = Yb[e];
  }

  float xr[DIMK];
  float x2 = 0.f;
#pragma unroll
  for (int k4 = 0; k4 < DIMK; k4 += 4) {
    float4 v = *reinterpret_cast<const float4*>(Xb + (size_t)tt * DIMK + k4);
    xr[k4] = v.x; xr[k4 + 1] = v.y; xr[k4 + 2] = v.z; xr[k4 + 3] = v.w;
  }
#pragma unroll
  for (int k = 0; k < DIMK; k++) x2 += xr[k] * xr[k];

  __syncthreads();

  if (half == 0) {
    float a = 0.f;
#pragma unroll
    for (int k = 0; k < DIMK; k++) {
      float yv = Ys[k * YS_STRIDE + tt];
      a += yv * yv;
    }
    y2s[tt] = a;
  }
  __syncthreads();

  float* gout = g_Ddiag + (size_t)b * (DPITCH * SEQ);
  const int w = tt >> 5, lane = tt & 31;

  for (int jj = 0; jj < 8; jj++) {
    const int jb = half * 8 + jj;
    float acc[8];
#pragma unroll
    for (int m = 0; m < 8; m++) acc[m] = 0.f;

#pragma unroll
    for (int k = 0; k < DIMK; k++) {
      const float4 ya = *reinterpret_cast<const float4*>(&Ys[k * YS_STRIDE + jb * 8]);
      const float4 yb = *reinterpret_cast<const float4*>(&Ys[k * YS_STRIDE + jb * 8 + 4]);
      const float xv = xr[k];
      acc[0] += xv * ya.x; acc[1] += xv * ya.y;
      acc[2] += xv * ya.z; acc[3] += xv * ya.w;
      acc[4] += xv * yb.x; acc[5] += xv * yb.y;
      acc[6] += xv * yb.z; acc[7] += xv * yb.w;
    }

#pragma unroll
    for (int m = 0; m < 8; m++) {
      Dst[half][tt * DST_STRIDE + m] = x2 + y2s[jb * 8 + m] - 2.f * acc[m];
    }
    __syncthreads();

    const int p0 = i0 + j0 + jb * 8;
    for (int dbase = w * 4; dbase < TI + 8 - 1; dbase += 16) {
      int d = dbase + (lane >> 3);
      int q = lane & 7;
      if (d < TI + 8 - 1) {
        int lo = d - 7 < 0 ? 0 : d - 7;
        int hi = d < TI - 1 ? d : TI - 1;
        int irow = lo + q;
        if (irow <= hi) {
          gout[(size_t)(p0 + d) * SEQ + (i0 + irow)] =
              Dst[half][irow * DST_STRIDE + (d - irow)];
        }
      }
    }
    __syncthreads();
  }
}

// ---------------------------------------------------------------------------
// Phase 2: wavefront DP — R2 verbatim (reproduced 3x at ~136us, regs=93).
// 4 warps, 4 consecutive rows per thread; parity-double-buffered smem
// mailboxes; one barrier per step; 8-deep float4 register prefetch.
// Base-2 scaled domain (R' = R * log2e).
// ---------------------------------------------------------------------------
__global__ __launch_bounds__(128) void softdtw_dp_kernel(float* __restrict__ out) {
  const int b = blockIdx.x;
  const int t = threadIdx.x;
  const int lane = t & 31, w = t >> 5;

  __shared__ float sb1[2][4];
  __shared__ float sb2[2][4];
  if (t < 8) {
    (&sb1[0][0])[t] = BIGF;
    (&sb2[0][0])[t] = BIGF;
  }

  float v1[4], v2[4];
#pragma unroll
  for (int k = 0; k < 4; k++) { v1[k] = BIGF; v2[k] = BIGF; }

  const float* base = g_Ddiag + (size_t)b * (DPITCH * SEQ) + 4 * t;
  __syncthreads();

#define DP_STEP(P, G4)                                                        \
  {                                                                           \
    const int rs = (P) & 1;                                                   \
    float nb1 = __shfl_up_sync(0xffffffffu, v1[3], 1);                        \
    float nb2 = __shfl_up_sync(0xffffffffu, v2[3], 1);                        \
    if (lane == 0) {                                                          \
      nb1 = (w == 0) ? BIGF : sb1[rs][w - 1];                                 \
      nb2 = (w == 0) ? (((P) == 0) ? 0.0f : BIGF) : sb2[rs][w - 1];           \
    }                                                                         \
    float sm0 = softmin3s(nb2,   nb1,   v1[0]);                               \
    float sm1 = softmin3s(v2[0], v1[0], v1[1]);                               \
    float sm2 = softmin3s(v2[1], v1[1], v1[2]);                               \
    float sm3 = softmin3s(v2[2], v1[2], v1[3]);                               \
    unsigned pr = (unsigned)((P) - 4 * t);                                    \
    float n0 = (pr      < (unsigned)SEQ) ? fmaf((G4).x, L2E, sm0) : BIGF;     \
    float n1 = (pr - 1u < (unsigned)SEQ) ? fmaf((G4).y, L2E, sm1) : BIGF;     \
    float n2 = (pr - 2u < (unsigned)SEQ) ? fmaf((G4).z, L2E, sm2) : BIGF;     \
    float n3 = (pr - 3u < (unsigned)SEQ) ? fmaf((G4).w, L2E, sm3) : BIGF;     \
    v2[0] = v1[0]; v2[1] = v1[1]; v2[2] = v1[2]; v2[3] = v1[3];               \
    v1[0] = n0;    v1[1] = n1;    v1[2] = n2;    v1[3] = n3;                  \
    if (lane == 31) { sb1[rs ^ 1][w] = v1[3]; sb2[rs ^ 1][w] = v2[3]; }       \
    __syncthreads();                                                          \
  }

  // prefetch pipeline: groups of 8 diagonals
  float4 cur[8];
#pragma unroll
  for (int j = 0; j < 8; j++)
    cur[j] = *reinterpret_cast<const float4*>(base + (size_t)j * SEQ);

  for (int g = 0; g < 127; ++g) {
    float4 nxt[8];
#pragma unroll
    for (int j = 0; j < 8; j++)
      nxt[j] = *reinterpret_cast<const float4*>(base + (size_t)(8 * (g + 1) + j) * SEQ);
#pragma unroll
    for (int j = 0; j < 8; j++) {
      const int p = 8 * g + j;
      DP_STEP(p, cur[j]);
    }
#pragma unroll
    for (int j = 0; j < 8; j++) cur[j] = nxt[j];
  }
  // epilogue: p = 1016 .. 1022
#pragma unroll
  for (int j = 0; j < 7; j++) {
    const int p = 1016 + j;
    DP_STEP(p, cur[j]);
  }

  if (t == 127) out[b] = v1[3] * LN2;  // R(511,511), back to nat domain
#undef DP_STEP
}

// ---------------------------------------------------------------------------
extern "C" void kernel_launch(void* const* d_in, const int* in_sizes, int n_in,
                              void* d_out, int out_size) {
  const float* X = (const float*)d_in[0];
  const float* Y = (const float*)d_in[1];
  float* out = (float*)d_out;

  dim3 grid_g(SEQ / TI, SEQ / TJ, BATCH);
  gemm_diag_kernel<<<grid_g, 256>>>(X, Y);
  softdtw_dp_kernel<<<BATCH, 128>>>(out);
}